// round 7
// baseline (speedup 1.0000x reference)
#include <cuda_runtime.h>
#include <cuda_fp16.h>
#include <cstdint>
#include <mma.h>

using namespace nvcuda;

// ---------------- problem constants ----------------
#define BATCH 1024
#define TSTEPS 256
#define DPART 64
#define ADIM 8
#define HDIM 256
#define KTOT 321
#define NPACK 1024       // 256 units * 4 panels; slice layout [r32|z32|nf32|hpn32]

// cluster decomposition
#define CSIZE 8          // CTAs per cluster; each owns 128 packed cols (32 units)
#define NCLUST 16        // clusters; each owns 64 batch rows
#define MROWS 64
#define NCOLS 128
#define NTHREADS 512     // 16 warps

// SMEM strides (elements)
#define HS_LD 264        // halves (256 + 8)
#define PS_LD 88         // halves (80 + 8)
#define WS_LD 136        // halves (128 + 8)
#define CS_LD 132        // floats (128 + 4)
#define KPAD 336

// SMEM byte offsets
#define SM_HS 0
#define SM_PS (2 * MROWS * HS_LD * 2)
#define SM_WS (SM_PS + MROWS * PS_LD * 2)
#define SM_CS (SM_WS + KPAD * WS_LD * 2)
#define SMEM_BYTES (SM_CS + MROWS * CS_LD * 4)   // ~204 KB

// ---------------- device scratch ----------------
__device__ __half g_Wph[KPAD * NPACK];     // packed fp16 GRU weights
__device__ __half g_hx[BATCH * HDIM];      // final h (fp16)
__device__ float  g_W1t[2 * 288 * 256];
__device__ float  g_W2t[2 * 256 * 256];
__device__ float  g_mlp1[2 * BATCH * 256];
__device__ float  g_mlp2[2 * BATCH * 256];

// ---------------- GRU weight packing (same layout as R5) ----------------
__global__ void prep_weights(const float* __restrict__ Wi, const float* __restrict__ Wh) {
    int idx = blockIdx.x * blockDim.x + threadIdx.x;
    if (idx >= KPAD * NPACK) return;
    int k = idx / NPACK;
    int col = idx % NPACK;
    int hb = col >> 7;
    int rem = col & 127;
    int panel = rem >> 5;
    int u = rem & 31;
    int j = hb * 32 + u;
    float w = 0.0f;
    if (panel < 3) {
        int g = j + panel * 256;
        if (k < 256)          w = Wh[k * 768 + g];
        else if (k < KTOT)    w = Wi[(k - 256) * 768 + g];
    } else {
        if (k < 256)          w = Wh[k * 768 + (j + 512)];
    }
    g_Wph[idx] = __float2half(w);
}

// ---------------- MLP weight packing ----------------
__global__ void prep_mlp(const float* __restrict__ W1, const float* __restrict__ W2) {
    int idx = blockIdx.x * blockDim.x + threadIdx.x;
    const int N1 = 2 * 288 * 256;
    const int N2 = 2 * 256 * 256;
    if (idx < N1) {
        int c = idx / (288 * 256);
        int rem = idx % (288 * 256);
        int k = rem / 256, n = rem % 256;
        float w = (k < 265) ? W1[((size_t)c * 265 + k) * 256 + n] : 0.0f;
        g_W1t[idx] = wmma::__float_to_tf32(w);
    } else if (idx < N1 + N2) {
        int i2 = idx - N1;
        g_W2t[i2] = wmma::__float_to_tf32(W2[i2]);
    }
}

// ---------------- persistent GRU kernel ----------------
__global__ void __cluster_dims__(CSIZE, 1, 1) __launch_bounds__(NTHREADS, 1)
gru_persistent(const float* __restrict__ particles,   // [B,T,DP]
               const float* __restrict__ pweights,    // [B,T]
               const float* __restrict__ bi,          // [768]
               const float* __restrict__ bhn)         // [256]
{
    extern __shared__ char smem_raw[];
    __half* Hs = (__half*)(smem_raw + SM_HS);   // [2][MROWS][HS_LD]
    __half* Ps = (__half*)(smem_raw + SM_PS);   // [MROWS][PS_LD]
    __half* Ws = (__half*)(smem_raw + SM_WS);   // [KPAD][WS_LD]
    float*  Cs = (float*)(smem_raw + SM_CS);    // [MROWS][CS_LD]

    const int tid  = threadIdx.x;
    const int rnk  = blockIdx.x & (CSIZE - 1);
    const int cl   = blockIdx.x >> 3;
    const int row0 = cl * MROWS;
    const int col0 = rnk * NCOLS;

    const int warp = tid >> 5;
    const int wr   = warp & 3;     // GEMM row tile: rows wr*16
    const int wc   = warp >> 2;    // GEMM col group: cols wc*32

    // ---- epilogue mapping: 1 row x 4 units per thread ----
    const int erow = tid >> 3;          // 0..63
    const int qg   = tid & 7;           // unit group: local units 4qg..4qg+3
    const int j0   = rnk * 32 + qg * 4; // first global unit (mult of 4)
    const float4 bir4 = *(const float4*)(bi + j0);
    const float4 biz4 = *(const float4*)(bi + 256 + j0);
    const float4 bin4 = *(const float4*)(bi + 512 + j0);
    const float4 bh4  = *(const float4*)(bhn + j0);
    const float br_[4] = {bir4.x, bir4.y, bir4.z, bir4.w};
    const float bz_[4] = {biz4.x, biz4.y, biz4.z, biz4.w};
    const float bn_[4] = {bin4.x, bin4.y, bin4.z, bin4.w};
    const float bh_[4] = {bh4.x,  bh4.y,  bh4.z,  bh4.w};

    // shared-space u32 base of Hs (for mapa)
    unsigned int hs_u32;
    asm("{ .reg .u64 t; cvta.to.shared.u64 t, %1; cvt.u32.u64 %0, t; }"
        : "=r"(hs_u32) : "l"(Hs));

    // ---- load weight slice (once) ----
    for (int i = tid; i < KPAD * 16; i += NTHREADS) {
        int r = i >> 4, q = i & 15;
        ((uint4*)(Ws + r * WS_LD))[q] =
            ((const uint4*)(g_Wph + (size_t)r * NPACK + col0))[q];
    }
    // ---- zero Hs[0] h-columns ----
    for (int i = tid; i < MROWS * 32; i += NTHREADS) {
        int r = i >> 5, q = i & 31;
        ((uint4*)(Hs + r * HS_LD))[q] = make_uint4(0, 0, 0, 0);
    }
    // ---- zero all of Ps (cols 65..87 stay zero forever) ----
    for (int i = tid; i < MROWS * 11; i += NTHREADS) {
        int r = i / 11, q = i % 11;
        ((uint4*)(Ps + r * PS_LD))[q] = make_uint4(0, 0, 0, 0);
    }
    __syncthreads();

    // ---- fill particles for t=0 ----
    for (int i = tid; i < MROWS * 16; i += NTHREADS) {
        int r = i >> 4, q = i & 15;
        float4 v = ((const float4*)(particles + ((size_t)(row0 + r) * TSTEPS + 0) * DPART))[q];
        __half2* dst = (__half2*)(Ps + r * PS_LD + q * 4);
        dst[0] = __floats2half2_rn(v.x, v.y);
        dst[1] = __floats2half2_rn(v.z, v.w);
    }
    if (tid < MROWS)
        Ps[tid * PS_LD + 64] = __float2half(pweights[(size_t)(row0 + tid) * TSTEPS + 0]);
    __syncthreads();

    // ---- accumulators: acc (even K chunks + x part), accB (odd K chunks) ----
    wmma::fragment<wmma::accumulator, 16, 16, 16, float> acc[2], accB[2];

    // ---- x-GEMM for t=0 ----
    wmma::fill_fragment(acc[0], 0.0f);
    wmma::fill_fragment(acc[1], 0.0f);
    wmma::fill_fragment(accB[0], 0.0f);
    wmma::fill_fragment(accB[1], 0.0f);
#pragma unroll
    for (int kk = 0; kk < 80; kk += 16) {
        wmma::fragment<wmma::matrix_a, 16, 16, 16, __half, wmma::row_major> af;
        wmma::load_matrix_sync(af, Ps + (wr * 16) * PS_LD + kk, PS_LD);
#pragma unroll
        for (int ct = 0; ct < 2; ct++) {
            wmma::fragment<wmma::matrix_b, 16, 16, 16, __half, wmma::row_major> bf;
            wmma::load_matrix_sync(bf, Ws + (256 + kk) * WS_LD + wc * 32 + ct * 16, WS_LD);
            wmma::mma_sync(acc[ct], af, bf, acc[ct]);
        }
    }

    // pre-loop arrive: pairs with loop-head wait at t=0
    asm volatile("barrier.cluster.arrive.aligned;" ::: "memory");

    for (int t = 0; t < TSTEPS; ++t) {
        const int p = t & 1;
        const __half* __restrict__ Hin = Hs + p * MROWS * HS_LD;

        // ---- wait: h_t is now complete in Hs[p] (peers' scatter done) ----
        asm volatile("barrier.cluster.wait.aligned;" ::: "memory");

        // ---- h-GEMM: acc/accB += Hin[64,256] @ Ws[0:256]  ----
#pragma unroll
        for (int kk = 0; kk < 256; kk += 32) {
            {
                wmma::fragment<wmma::matrix_a, 16, 16, 16, __half, wmma::row_major> af;
                wmma::load_matrix_sync(af, Hin + (wr * 16) * HS_LD + kk, HS_LD);
#pragma unroll
                for (int ct = 0; ct < 2; ct++) {
                    wmma::fragment<wmma::matrix_b, 16, 16, 16, __half, wmma::row_major> bf;
                    wmma::load_matrix_sync(bf, Ws + kk * WS_LD + wc * 32 + ct * 16, WS_LD);
                    wmma::mma_sync(acc[ct], af, bf, acc[ct]);
                }
            }
            {
                wmma::fragment<wmma::matrix_a, 16, 16, 16, __half, wmma::row_major> af;
                wmma::load_matrix_sync(af, Hin + (wr * 16) * HS_LD + kk + 16, HS_LD);
#pragma unroll
                for (int ct = 0; ct < 2; ct++) {
                    wmma::fragment<wmma::matrix_b, 16, 16, 16, __half, wmma::row_major> bf;
                    wmma::load_matrix_sync(bf, Ws + (kk + 16) * WS_LD + wc * 32 + ct * 16, WS_LD);
                    wmma::mma_sync(accB[ct], af, bf, accB[ct]);
                }
            }
        }
        // merge accB into acc and store C
#pragma unroll
        for (int ct = 0; ct < 2; ct++) {
#pragma unroll
            for (int e = 0; e < acc[ct].num_elements; ++e)
                acc[ct].x[e] += accB[ct].x[e];
            wmma::store_matrix_sync(Cs + (wr * 16) * CS_LD + wc * 32 + ct * 16,
                                    acc[ct], CS_LD, wmma::mem_row_major);
        }
        __syncthreads();

        // ---- gate epilogue: 1 row x 4 units per thread ----
        const float* Crow = Cs + erow * CS_LD + qg * 4;
        float4 vr = *(const float4*)(Crow);
        float4 vz = *(const float4*)(Crow + 32);
        float4 vn = *(const float4*)(Crow + 64);
        float4 vh = *(const float4*)(Crow + 96);
        const float cr_[4] = {vr.x, vr.y, vr.z, vr.w};
        const float cz_[4] = {vz.x, vz.y, vz.z, vz.w};
        const float cn_[4] = {vn.x, vn.y, vn.z, vn.w};
        const float ch_[4] = {vh.x, vh.y, vh.z, vh.w};

        uint2 hold = *(const uint2*)(Hin + erow * HS_LD + j0);
        __half2 ho01 = *(__half2*)&hold.x;
        __half2 ho23 = *(__half2*)&hold.y;
        const float ho_[4] = {__low2float(ho01), __high2float(ho01),
                              __low2float(ho23), __high2float(ho23)};

        float hn_[4];
#pragma unroll
        for (int s = 0; s < 4; ++s) {
            float rg = __fdividef(1.0f, 1.0f + __expf(-(cr_[s] + br_[s])));
            float zg = __fdividef(1.0f, 1.0f + __expf(-(cz_[s] + bz_[s])));
            float a  = (cn_[s] + bn_[s] - ch_[s]) + rg * (ch_[s] + bh_[s]);
            a = fminf(fmaxf(a, -15.0f), 15.0f);
            float e2 = __expf(-2.0f * a);
            float ng = __fdividef(1.0f - e2, 1.0f + e2);
            hn_[s] = (1.0f - zg) * ng + zg * ho_[s];
        }
        __half2 o01 = __floats2half2_rn(hn_[0], hn_[1]);
        __half2 o23 = __floats2half2_rn(hn_[2], hn_[3]);
        unsigned int w0 = *(unsigned int*)&o01;
        unsigned int w1 = *(unsigned int*)&o23;
        unsigned long long val64 = ((unsigned long long)w1 << 32) | w0;

        if (t < TSTEPS - 1) {
            // scatter h_{t+1} slice to all 8 CTAs (b64)
            unsigned int off = hs_u32 + (unsigned int)((p ^ 1) * MROWS * HS_LD) * 2u
                             + (unsigned int)(erow * HS_LD + j0) * 2u;
#pragma unroll
            for (int d = 0; d < CSIZE; ++d) {
                unsigned int rem;
                asm("mapa.shared::cluster.u32 %0, %1, %2;" : "=r"(rem) : "r"(off), "r"(d));
                asm volatile("st.shared::cluster.b64 [%0], %1;" :: "r"(rem), "l"(val64) : "memory");
            }
        } else {
            // final step: publish h to global for the MLP
            *(uint2*)(g_hx + (size_t)(row0 + erow) * HDIM + j0) = make_uint2(w0, w1);
        }

        // release scatter
        asm volatile("barrier.cluster.arrive.aligned;" ::: "memory");

        // ---- hidden behind peers' window: ingest particles(t+1) + x-GEMM(t+1) ----
        if (t < TSTEPS - 1) {
            __syncthreads();   // epilogue Cs reads done before next store; Ps safe to refill
            for (int i = tid; i < MROWS * 16; i += NTHREADS) {
                int r = i >> 4, q = i & 15;
                float4 v = ((const float4*)(particles +
                            ((size_t)(row0 + r) * TSTEPS + (t + 1)) * DPART))[q];
                __half2* dst = (__half2*)(Ps + r * PS_LD + q * 4);
                dst[0] = __floats2half2_rn(v.x, v.y);
                dst[1] = __floats2half2_rn(v.z, v.w);
            }
            if (tid < MROWS)
                Ps[tid * PS_LD + 64] =
                    __float2half(pweights[(size_t)(row0 + tid) * TSTEPS + (t + 1)]);
            __syncthreads();

            wmma::fill_fragment(acc[0], 0.0f);
            wmma::fill_fragment(acc[1], 0.0f);
            wmma::fill_fragment(accB[0], 0.0f);
            wmma::fill_fragment(accB[1], 0.0f);
#pragma unroll
            for (int kk = 0; kk < 80; kk += 16) {
                wmma::fragment<wmma::matrix_a, 16, 16, 16, __half, wmma::row_major> af;
                wmma::load_matrix_sync(af, Ps + (wr * 16) * PS_LD + kk, PS_LD);
#pragma unroll
                for (int ct = 0; ct < 2; ct++) {
                    wmma::fragment<wmma::matrix_b, 16, 16, 16, __half, wmma::row_major> bf;
                    wmma::load_matrix_sync(bf, Ws + (256 + kk) * WS_LD + wc * 32 + ct * 16, WS_LD);
                    wmma::mma_sync(acc[ct], af, bf, acc[ct]);
                }
            }
        }
    }

    // final wait: pairs with everyone's last arrive; guarantees no in-flight
    // remote stores target this CTA's SMEM at exit.
    asm volatile("barrier.cluster.wait.aligned;" ::: "memory");
}

// ---------------- MLP layers: tf32 wmma, 64x64 tile, BK=32 ----------------
__global__ void __launch_bounds__(256) mlp_layer_t(
    const float* __restrict__ action, const float* __restrict__ time_idx,
    const float* __restrict__ bias, int KP, int mode)
{
    __shared__ float As[64][40];
    __shared__ float Bs[32][72];
    __shared__ float stage[64][68];

    const int c = blockIdx.z;
    const int rowb = blockIdx.x * 64;
    const int colb = blockIdx.y * 64;
    const int tid = threadIdx.x;
    const int warp = tid >> 5;
    const int wr = warp & 3;
    const int wc = warp >> 2;

    wmma::fragment<wmma::accumulator, 16, 16, 8, float> acc[2];
    wmma::fill_fragment(acc[0], 0.0f);
    wmma::fill_fragment(acc[1], 0.0f);

    const float* Wsrc = (mode == 0) ? g_W1t + (size_t)c * 288 * 256
                                    : g_W2t + (size_t)c * 256 * 256;

    for (int k0 = 0; k0 < KP; k0 += 32) {
        for (int i = tid; i < 64 * 32; i += 256) {
            int r = i >> 5, k = i & 31;
            int d = k0 + k;
            float v = 0.0f;
            if (mode == 0) {
                if (d < 256)       v = __half2float(g_hx[(size_t)(rowb + r) * HDIM + d]);
                else if (d < 264)  v = action[(rowb + r) * ADIM + (d - 256)];
                else if (d == 264) v = time_idx[rowb + r] * 0.01f;
            } else {
                v = g_mlp1[((size_t)c * BATCH + rowb + r) * 256 + d];
            }
            As[r][k] = wmma::__float_to_tf32(v);
        }
        for (int i = tid; i < 32 * 64; i += 256) {
            int kk = i >> 6, cc = i & 63;
            Bs[kk][cc] = Wsrc[(size_t)(k0 + kk) * 256 + colb + cc];
        }
        __syncthreads();
#pragma unroll
        for (int kk = 0; kk < 32; kk += 8) {
            wmma::fragment<wmma::matrix_a, 16, 16, 8, wmma::precision::tf32, wmma::row_major> af;
            wmma::load_matrix_sync(af, &As[wr * 16][kk], 40);
#pragma unroll
            for (int ct = 0; ct < 2; ct++) {
                wmma::fragment<wmma::matrix_b, 16, 16, 8, wmma::precision::tf32, wmma::row_major> bf;
                wmma::load_matrix_sync(bf, &Bs[kk][wc * 32 + ct * 16], 72);
                wmma::mma_sync(acc[ct], af, bf, acc[ct]);
            }
        }
        __syncthreads();
    }

#pragma unroll
    for (int ct = 0; ct < 2; ct++)
        wmma::store_matrix_sync(&stage[wr * 16][wc * 32 + ct * 16], acc[ct], 68,
                                wmma::mem_row_major);
    __syncthreads();

    float* dst = (mode == 0) ? g_mlp1 : g_mlp2;
    for (int i = tid; i < 64 * 64; i += 256) {
        int r = i >> 6, col = i & 63;
        float v = stage[r][col] + bias[c * 256 + colb + col];
        dst[((size_t)c * BATCH + rowb + r) * 256 + colb + col] = fmaxf(v, 0.0f);
    }
}

// ---------------- final projection ----------------
__global__ void mlp_out(const float* __restrict__ W3, const float* __restrict__ b3,
                        float* __restrict__ out)
{
    int gw   = (blockIdx.x * blockDim.x + threadIdx.x) >> 5;
    int lane = threadIdx.x & 31;
    if (gw >= 2 * BATCH) return;
    int c = gw >> 10;
    int b = gw & 1023;
    const float* v = g_mlp2 + ((size_t)c * BATCH + b) * 256;
    const float* w = W3 + (size_t)c * 256;
    float s = 0.0f;
    for (int i = lane; i < 256; i += 32) s += v[i] * w[i];
#pragma unroll
    for (int o = 16; o; o >>= 1) s += __shfl_xor_sync(0xffffffffu, s, o);
    if (lane == 0) out[b * 2 + c] = s + b3[c];
}

// ---------------- launch ----------------
extern "C" void kernel_launch(void* const* d_in, const int* in_sizes, int n_in,
                              void* d_out, int out_size)
{
    const float* particles = (const float*)d_in[0];
    const float* weights   = (const float*)d_in[1];
    const float* action    = (const float*)d_in[2];
    const float* time_idx  = (const float*)d_in[3];
    const float* Wi        = (const float*)d_in[4];
    const float* bi        = (const float*)d_in[5];
    const float* Wh        = (const float*)d_in[6];
    const float* bhn       = (const float*)d_in[7];
    const float* W1        = (const float*)d_in[8];
    const float* b1        = (const float*)d_in[9];
    const float* W2        = (const float*)d_in[10];
    const float* b2        = (const float*)d_in[11];
    const float* W3        = (const float*)d_in[12];
    const float* b3        = (const float*)d_in[13];
    float* out = (float*)d_out;

    cudaFuncSetAttribute(gru_persistent,
                         cudaFuncAttributeMaxDynamicSharedMemorySize, SMEM_BYTES);

    prep_weights<<<(KPAD * NPACK + 255) / 256, 256>>>(Wi, Wh);
    prep_mlp<<<(2 * 288 * 256 + 2 * 256 * 256 + 255) / 256, 256>>>(W1, W2);

    gru_persistent<<<NCLUST * CSIZE, NTHREADS, SMEM_BYTES>>>(particles, weights, bi, bhn);

    mlp_layer_t<<<dim3(16, 4, 2), 256>>>(action, time_idx, b1, 288, 0);
    mlp_layer_t<<<dim3(16, 4, 2), 256>>>(action, time_idx, b2, 256, 1);
    mlp_out<<<(2 * BATCH * 32 + 255) / 256, 256>>>(W3, b3, out);
}

// round 8
// speedup vs baseline: 1.2413x; 1.2413x over previous
#include <cuda_runtime.h>
#include <cuda_fp16.h>
#include <cstdint>
#include <mma.h>

using namespace nvcuda;

// ---------------- problem constants ----------------
#define BATCH 1024
#define TSTEPS 256
#define DPART 64
#define ADIM 8
#define HDIM 256
#define CSIZE 8          // CTAs per cluster; each owns 96 cols (32 units x {r,z,p})
#define NCLUST 16        // clusters; each owns 64 batch rows
#define MROWS 64
#define NTHREADS 256     // 8 warps: 4 row groups x 2 col groups (48 cols each)

// SMEM layout (byte strides / offsets)
#define HS_STRIDE 528    // 264 halves (256 + 8 pad)
#define PS_STRIDE 176    // 88 halves (80 + 8 pad)
#define WS_STRIDE 208    // 104 halves (96 + 8 pad)
#define SM_HS 0
#define SM_PS (SM_HS + MROWS * HS_STRIDE)     // 33792
#define SM_WH (SM_PS + MROWS * PS_STRIDE)     // 45056
#define SM_WX (SM_WH + 256 * WS_STRIDE)       // 98304
#define SMEM_BYTES (SM_WX + 80 * WS_STRIDE)   // 114944

// ---------------- device scratch ----------------
__device__ __half g_Whp[CSIZE * 256 * 96];   // h-weights, per-rank packed [rnk][k][96]
__device__ __half g_Wxp[CSIZE * 80 * 96];    // x-weights, per-rank packed [rnk][k][96]
__device__ __half g_hpp[2][BATCH * HDIM];    // h ping-pong (fp16)
__device__ float  g_W1t[2 * 288 * 256];
__device__ float  g_W2t[2 * 256 * 256];
__device__ float  g_mlp1[2 * BATCH * 256];
__device__ float  g_mlp2[2 * BATCH * 256];
__device__ int    g_sink;

// ---------------- PTX helpers ----------------
__device__ __forceinline__ unsigned smem_u32(const void* p) {
    unsigned a;
    asm("{ .reg .u64 t; cvta.to.shared.u64 t, %1; cvt.u32.u64 %0, t; }" : "=r"(a) : "l"(p));
    return a;
}
__device__ __forceinline__ void ldsm_x4(unsigned r[4], unsigned addr) {
    asm volatile("ldmatrix.sync.aligned.m8n8.x4.shared.b16 {%0,%1,%2,%3}, [%4];"
        : "=r"(r[0]), "=r"(r[1]), "=r"(r[2]), "=r"(r[3]) : "r"(addr));
}
__device__ __forceinline__ void ldsm_x4_t(unsigned r[4], unsigned addr) {
    asm volatile("ldmatrix.sync.aligned.m8n8.x4.trans.shared.b16 {%0,%1,%2,%3}, [%4];"
        : "=r"(r[0]), "=r"(r[1]), "=r"(r[2]), "=r"(r[3]) : "r"(addr));
}
__device__ __forceinline__ void mma16816(float c[4], const unsigned a[4],
                                         unsigned b0, unsigned b1) {
    asm volatile("mma.sync.aligned.m16n8k16.row.col.f32.f16.f16.f32 "
        "{%0,%1,%2,%3}, {%4,%5,%6,%7}, {%8,%9}, {%0,%1,%2,%3};"
        : "+f"(c[0]), "+f"(c[1]), "+f"(c[2]), "+f"(c[3])
        : "r"(a[0]), "r"(a[1]), "r"(a[2]), "r"(a[3]), "r"(b0), "r"(b1));
}

// ---------------- weight packing ----------------
// Rank slice: 96 cols = 2 col-groups x [r(16)|z(16)|p(16)] for 16 units each.
// col c: wcg=c/48, rem=c%48, panel=rem/16, uu=rem%16, unit j = rnk*32+wcg*16+uu.
// h-weights: Wh[k][panel*256+j]; x-weights: Wi[k][panel*256+j] (panel2 = Wi_n), k>=65 -> 0.
__global__ void prep_weights(const float* __restrict__ Wi, const float* __restrict__ Wh) {
    int idx = blockIdx.x * blockDim.x + threadIdx.x;
    const int NH = CSIZE * 256 * 96;
    const int NX = CSIZE * 80 * 96;
    if (idx < NH) {
        int rnk = idx / (256 * 96);
        int rem = idx % (256 * 96);
        int k = rem / 96, c = rem % 96;
        int wcg = c / 48, r2 = c % 48, panel = r2 / 16, uu = r2 % 16;
        int j = rnk * 32 + wcg * 16 + uu;
        g_Whp[idx] = __float2half(Wh[k * 768 + panel * 256 + j]);
    } else if (idx < NH + NX) {
        int i2 = idx - NH;
        int rnk = i2 / (80 * 96);
        int rem = i2 % (80 * 96);
        int k = rem / 96, c = rem % 96;
        int wcg = c / 48, r2 = c % 48, panel = r2 / 16, uu = r2 % 16;
        int j = rnk * 32 + wcg * 16 + uu;
        float w = (k < 65) ? Wi[k * 768 + panel * 256 + j] : 0.0f;
        g_Wxp[i2] = __float2half(w);
    }
}

__global__ void prep_mlp(const float* __restrict__ W1, const float* __restrict__ W2) {
    int idx = blockIdx.x * blockDim.x + threadIdx.x;
    const int N1 = 2 * 288 * 256;
    const int N2 = 2 * 256 * 256;
    if (idx < N1) {
        int c = idx / (288 * 256);
        int rem = idx % (288 * 256);
        int k = rem / 256, n = rem % 256;
        float w = (k < 265) ? W1[((size_t)c * 265 + k) * 256 + n] : 0.0f;
        g_W1t[idx] = wmma::__float_to_tf32(w);
    } else if (idx < N1 + N2) {
        g_W2t[idx - N1] = wmma::__float_to_tf32(W2[idx - N1]);
    }
}

__global__ void zero_h() {
    int i = blockIdx.x * blockDim.x + threadIdx.x;
    if (i < BATCH * HDIM) g_hpp[0][i] = __float2half(0.0f);
}

// dummy launches so gru_reg lands at ncu capture index 5
__global__ void warm_k(int v) {
    if (threadIdx.x == 0 && v == 123456789) g_sink = 1;  // never taken
}

// ---------------- persistent GRU: raw mma, register epilogue ----------------
__global__ void __cluster_dims__(CSIZE, 1, 1) __launch_bounds__(NTHREADS, 1)
gru_reg(const float* __restrict__ particles,   // [B,T,DP]
        const float* __restrict__ pweights,    // [B,T]
        const float* __restrict__ bi,          // [768]
        const float* __restrict__ bhn)         // [256]
{
    extern __shared__ char smem[];
    const unsigned sb = smem_u32(smem);
    char* HsB = smem + SM_HS;
    char* PsB = smem + SM_PS;

    const int tid  = threadIdx.x;
    const int lane = tid & 31;
    const int warp = tid >> 5;
    const int wr   = warp & 3;      // row group: rows wr*16
    const int wc   = warp >> 2;     // col group: cols wc*48
    const int rnk  = blockIdx.x & (CSIZE - 1);
    const int cl   = blockIdx.x >> 3;
    const int row0 = cl * MROWS;

    // ---- load weight slices into SMEM (once) ----
    for (int i = tid; i < 256 * 12; i += NTHREADS) {
        int r = i / 12, q = i % 12;
        *(uint4*)(smem + SM_WH + r * WS_STRIDE + q * 16) =
            *(const uint4*)(g_Whp + ((size_t)rnk * 256 + r) * 96 + q * 8);
    }
    for (int i = tid; i < 80 * 12; i += NTHREADS) {
        int r = i / 12, q = i % 12;
        *(uint4*)(smem + SM_WX + r * WS_STRIDE + q * 16) =
            *(const uint4*)(g_Wxp + ((size_t)rnk * 80 + r) * 96 + q * 8);
    }
    // ---- zero Ps pad cols 64..87 (bytes 128..175) ----
    for (int i = tid; i < MROWS * 3; i += NTHREADS) {
        int r = i / 3, q = i % 3;
        *(uint4*)(PsB + r * PS_STRIDE + 128 + q * 16) = make_uint4(0, 0, 0, 0);
    }
    // ---- fill Ps for t=0 ----
    for (int i = tid; i < MROWS * 16; i += NTHREADS) {
        int r = i >> 4, q = i & 15;
        float4 v = *(const float4*)(particles + ((size_t)(row0 + r) * TSTEPS + 0) * DPART + q * 4);
        __half2 h01 = __floats2half2_rn(v.x, v.y);
        __half2 h23 = __floats2half2_rn(v.z, v.w);
        *(uint2*)(PsB + r * PS_STRIDE + q * 8) =
            make_uint2(*(unsigned*)&h01, *(unsigned*)&h23);
    }
    if (tid < MROWS)
        *(__half*)(PsB + tid * PS_STRIDE + 128) =
            __float2half(pweights[(size_t)(row0 + tid) * TSTEPS + 0]);
    __syncthreads();

    // ---- per-thread ldmatrix base addresses ----
    const unsigned Ah = sb + SM_HS + (wr * 16 + (lane & 15)) * HS_STRIDE + (lane >> 4) * 16;
    const unsigned Ax = sb + SM_PS + (wr * 16 + (lane & 15)) * PS_STRIDE + (lane >> 4) * 16;
    const unsigned Bh = sb + SM_WH + (lane & 15) * WS_STRIDE + (wc * 48 + (lane >> 4) * 8) * 2;
    const unsigned Bx = sb + SM_WX + (lane & 15) * WS_STRIDE + (wc * 48 + (lane >> 4) * 8) * 2;

    // ---- per-thread epilogue constants ----
    const int ub    = (lane & 3) * 2;
    const int jbase = rnk * 32 + wc * 16;
    float bir[2][2], biz[2][2], bin[2][2], bhv[2][2];
#pragma unroll
    for (int nh = 0; nh < 2; ++nh)
#pragma unroll
        for (int pa = 0; pa < 2; ++pa) {
            int j = jbase + ub + nh * 8 + pa;
            bir[nh][pa] = bi[j];
            biz[nh][pa] = bi[256 + j];
            bin[nh][pa] = bi[512 + j];
            bhv[nh][pa] = bhn[j];
        }

    asm volatile("barrier.cluster.arrive.aligned;" ::: "memory");

    for (int t = 0; t < TSTEPS; ++t) {
        const int p = t & 1;

        float accP[3][2][4];   // panels r,z,hpn x n8-halves x 4 elems
        float accX[2][4];      // xn panel (x-GEMM only)
#pragma unroll
        for (int pn = 0; pn < 3; ++pn)
#pragma unroll
            for (int nh = 0; nh < 2; ++nh)
#pragma unroll
                for (int e = 0; e < 4; ++e) accP[pn][nh][e] = 0.0f;
#pragma unroll
        for (int nh = 0; nh < 2; ++nh)
#pragma unroll
            for (int e = 0; e < 4; ++e) accX[nh][e] = 0.0f;

        // ---- x-GEMM (h-independent; hides barrier skew) ----
#pragma unroll
        for (int kk = 0; kk < 5; ++kk) {
            unsigned a[4];
            ldsm_x4(a, Ax + kk * 32);
#pragma unroll
            for (int pn = 0; pn < 3; ++pn) {
                unsigned b[4];
                ldsm_x4_t(b, Bx + kk * 16 * WS_STRIDE + pn * 32);
                float* c0 = (pn < 2) ? accP[pn][0] : accX[0];
                float* c1 = (pn < 2) ? accP[pn][1] : accX[1];
                mma16816(c0, a, b[0], b[1]);
                mma16816(c1, a, b[2], b[3]);
            }
        }

        // ---- wait: h_t visible in g_hpp[p] ----
        asm volatile("barrier.cluster.wait.aligned;" ::: "memory");

        // ---- ingest h_t into SMEM (L2-fresh) ----
        const __half* __restrict__ hin = g_hpp[p];
#pragma unroll
        for (int i = tid; i < MROWS * 32; i += NTHREADS) {
            int r = i >> 5, q = i & 31;
            uint4 v = __ldcg((const uint4*)(hin + (size_t)(row0 + r) * HDIM + q * 8));
            *(uint4*)(HsB + r * HS_STRIDE + q * 16) = v;
        }
        __syncthreads();

        // ---- h-GEMM: accP += h_t[64,256] @ Wh_slice ----
#pragma unroll
        for (int kk = 0; kk < 16; ++kk) {
            unsigned a[4];
            ldsm_x4(a, Ah + kk * 32);
#pragma unroll
            for (int pn = 0; pn < 3; ++pn) {
                unsigned b[4];
                ldsm_x4_t(b, Bh + kk * 16 * WS_STRIDE + pn * 32);
                mma16816(accP[pn][0], a, b[0], b[1]);
                mma16816(accP[pn][1], a, b[2], b[3]);
            }
        }

        // ---- register gate epilogue + STG h_{t+1} ----
        __half* __restrict__ hout = g_hpp[p ^ 1];
#pragma unroll
        for (int nh = 0; nh < 2; ++nh) {
            const int jc = jbase + ub + nh * 8;
#pragma unroll
            for (int rr = 0; rr < 2; ++rr) {
                const int rloc = wr * 16 + (lane >> 2) + rr * 8;
                __half2 ho2 = *(const __half2*)(HsB + rloc * HS_STRIDE + jc * 2);
                float hov[2] = {__low2float(ho2), __high2float(ho2)};
                float hn[2];
#pragma unroll
                for (int s = 0; s < 2; ++s) {
                    int e = rr * 2 + s;
                    float rg = __fdividef(1.0f, 1.0f + __expf(-(accP[0][nh][e] + bir[nh][s])));
                    float zg = __fdividef(1.0f, 1.0f + __expf(-(accP[1][nh][e] + biz[nh][s])));
                    float a2 = (accX[nh][e] + bin[nh][s]) + rg * (accP[2][nh][e] + bhv[nh][s]);
                    a2 = fminf(fmaxf(a2, -15.0f), 15.0f);
                    float e2 = __expf(-2.0f * a2);
                    float ng = __fdividef(1.0f - e2, 1.0f + e2);
                    hn[s] = (1.0f - zg) * ng + zg * hov[s];
                }
                *(__half2*)(hout + (size_t)(row0 + rloc) * HDIM + jc) =
                    __floats2half2_rn(hn[0], hn[1]);
            }
        }
        __syncthreads();   // all Hs reads done before anyone's next-step ingest
        asm volatile("barrier.cluster.arrive.aligned;" ::: "memory");

        // ---- refill Ps for t+1 (hidden behind peers' window) ----
        if (t < TSTEPS - 1) {
            for (int i = tid; i < MROWS * 16; i += NTHREADS) {
                int r = i >> 4, q = i & 15;
                float4 v = *(const float4*)(particles +
                            ((size_t)(row0 + r) * TSTEPS + (t + 1)) * DPART + q * 4);
                __half2 h01 = __floats2half2_rn(v.x, v.y);
                __half2 h23 = __floats2half2_rn(v.z, v.w);
                *(uint2*)(PsB + r * PS_STRIDE + q * 8) =
                    make_uint2(*(unsigned*)&h01, *(unsigned*)&h23);
            }
            if (tid < MROWS)
                *(__half*)(PsB + tid * PS_STRIDE + 128) =
                    __float2half(pweights[(size_t)(row0 + tid) * TSTEPS + (t + 1)]);
            __syncthreads();
        }
    }
    // final h is in g_hpp[0] (256 steps, even)
}

// ---------------- MLP layers: tf32 wmma (unchanged from R5, reads g_hpp[0]) ----------------
__global__ void __launch_bounds__(256) mlp_layer_t(
    const float* __restrict__ action, const float* __restrict__ time_idx,
    const float* __restrict__ bias, int KP, int mode)
{
    __shared__ float As[64][40];
    __shared__ float Bs[32][72];
    __shared__ float stage[64][68];

    const int c = blockIdx.z;
    const int rowb = blockIdx.x * 64;
    const int colb = blockIdx.y * 64;
    const int tid = threadIdx.x;
    const int warp = tid >> 5;
    const int wr = warp & 3;
    const int wc = warp >> 2;

    wmma::fragment<wmma::accumulator, 16, 16, 8, float> acc[2];
    wmma::fill_fragment(acc[0], 0.0f);
    wmma::fill_fragment(acc[1], 0.0f);

    const float* Wsrc = (mode == 0) ? g_W1t + (size_t)c * 288 * 256
                                    : g_W2t + (size_t)c * 256 * 256;

    for (int k0 = 0; k0 < KP; k0 += 32) {
        for (int i = tid; i < 64 * 32; i += 256) {
            int r = i >> 5, k = i & 31;
            int d = k0 + k;
            float v = 0.0f;
            if (mode == 0) {
                if (d < 256)       v = __half2float(g_hpp[0][(size_t)(rowb + r) * HDIM + d]);
                else if (d < 264)  v = action[(rowb + r) * ADIM + (d - 256)];
                else if (d == 264) v = time_idx[rowb + r] * 0.01f;
            } else {
                v = g_mlp1[((size_t)c * BATCH + rowb + r) * 256 + d];
            }
            As[r][k] = wmma::__float_to_tf32(v);
        }
        for (int i = tid; i < 32 * 64; i += 256) {
            int kk = i >> 6, cc = i & 63;
            Bs[kk][cc] = Wsrc[(size_t)(k0 + kk) * 256 + colb + cc];
        }
        __syncthreads();
#pragma unroll
        for (int kk = 0; kk < 32; kk += 8) {
            wmma::fragment<wmma::matrix_a, 16, 16, 8, wmma::precision::tf32, wmma::row_major> af;
            wmma::load_matrix_sync(af, &As[wr * 16][kk], 40);
#pragma unroll
            for (int ct = 0; ct < 2; ct++) {
                wmma::fragment<wmma::matrix_b, 16, 16, 8, wmma::precision::tf32, wmma::row_major> bf;
                wmma::load_matrix_sync(bf, &Bs[kk][wc * 32 + ct * 16], 72);
                wmma::mma_sync(acc[ct], af, bf, acc[ct]);
            }
        }
        __syncthreads();
    }

#pragma unroll
    for (int ct = 0; ct < 2; ct++)
        wmma::store_matrix_sync(&stage[wr * 16][wc * 32 + ct * 16], acc[ct], 68,
                                wmma::mem_row_major);
    __syncthreads();

    float* dst = (mode == 0) ? g_mlp1 : g_mlp2;
    for (int i = tid; i < 64 * 64; i += 256) {
        int r = i >> 6, col = i & 63;
        float v = stage[r][col] + bias[c * 256 + colb + col];
        dst[((size_t)c * BATCH + rowb + r) * 256 + colb + col] = fmaxf(v, 0.0f);
    }
}

// ---------------- final projection ----------------
__global__ void mlp_out(const float* __restrict__ W3, const float* __restrict__ b3,
                        float* __restrict__ out)
{
    int gw   = (blockIdx.x * blockDim.x + threadIdx.x) >> 5;
    int lane = threadIdx.x & 31;
    if (gw >= 2 * BATCH) return;
    int c = gw >> 10;
    int b = gw & 1023;
    const float* v = g_mlp2 + ((size_t)c * BATCH + b) * 256;
    const float* w = W3 + (size_t)c * 256;
    float s = 0.0f;
    for (int i = lane; i < 256; i += 32) s += v[i] * w[i];
#pragma unroll
    for (int o = 16; o; o >>= 1) s += __shfl_xor_sync(0xffffffffu, s, o);
    if (lane == 0) out[b * 2 + c] = s + b3[c];
}

// ---------------- launch ----------------
extern "C" void kernel_launch(void* const* d_in, const int* in_sizes, int n_in,
                              void* d_out, int out_size)
{
    const float* particles = (const float*)d_in[0];
    const float* weights   = (const float*)d_in[1];
    const float* action    = (const float*)d_in[2];
    const float* time_idx  = (const float*)d_in[3];
    const float* Wi        = (const float*)d_in[4];
    const float* bi        = (const float*)d_in[5];
    const float* Wh        = (const float*)d_in[6];
    const float* bhn       = (const float*)d_in[7];
    const float* W1        = (const float*)d_in[8];
    const float* b1        = (const float*)d_in[9];
    const float* W2        = (const float*)d_in[10];
    const float* b2        = (const float*)d_in[11];
    const float* W3        = (const float*)d_in[12];
    const float* b3        = (const float*)d_in[13];
    float* out = (float*)d_out;

    cudaFuncSetAttribute(gru_reg, cudaFuncAttributeMaxDynamicSharedMemorySize, SMEM_BYTES);

    const int NWT = CSIZE * 256 * 96 + CSIZE * 80 * 96;
    prep_weights<<<(NWT + 255) / 256, 256>>>(Wi, Wh);                      // launch 0
    prep_mlp<<<(2 * 288 * 256 + 2 * 256 * 256 + 255) / 256, 256>>>(W1, W2); // 1
    zero_h<<<(BATCH * HDIM + 255) / 256, 256>>>();                          // 2
    warm_k<<<1, 32>>>(0);                                                   // 3
    warm_k<<<1, 32>>>(0);                                                   // 4
    gru_reg<<<NCLUST * CSIZE, NTHREADS, SMEM_BYTES>>>(particles, weights, bi, bhn); // 5 (ncu)

    mlp_layer_t<<<dim3(16, 4, 2), 256>>>(action, time_idx, b1, 288, 0);
    mlp_layer_t<<<dim3(16, 4, 2), 256>>>(action, time_idx, b2, 256, 1);
    mlp_out<<<(2 * BATCH * 32 + 255) / 256, 256>>>(W3, b3, out);
}

// round 9
// speedup vs baseline: 1.4965x; 1.2056x over previous
#include <cuda_runtime.h>
#include <cuda_fp16.h>
#include <cstdint>
#include <mma.h>

using namespace nvcuda;

// ---------------- problem constants ----------------
#define BATCH 1024
#define TSTEPS 256
#define DPART 64
#define ADIM 8
#define HDIM 256
#define CSIZE 8          // CTAs per cluster; each owns 96 cols (32 units x {r,z,p})
#define NCLUST 16        // clusters; each owns 64 batch rows
#define MROWS 64
#define NTHREADS 256     // 8 warps: 4 row pairs x 2 col groups (48 cols each)

// SMEM layout (byte strides / offsets)
#define HS_STRIDE 528    // 264 halves (256 + 8 pad)
#define PS_STRIDE 176    // 88 halves (80 + 8 pad)
#define WS_STRIDE 208    // 104 halves (96 + 8 pad)
#define SM_HS 0
#define SM_PS (SM_HS + MROWS * HS_STRIDE)     // 33792
#define SM_WH (SM_PS + MROWS * PS_STRIDE)     // 45056
#define SM_WX (SM_WH + 256 * WS_STRIDE)       // 98304
#define SMEM_BYTES (SM_WX + 80 * WS_STRIDE)   // 114944

// ---------------- device scratch ----------------
__device__ __half g_Whp[CSIZE * 256 * 96];   // h-weights, per-rank packed [rnk][k][96]
__device__ __half g_Wxp[CSIZE * 80 * 96];    // x-weights, per-rank packed [rnk][k][96]
__device__ __half g_hpp[2][BATCH * HDIM];    // h ping-pong (fp16)
__device__ float  g_W1t[2 * 288 * 256];
__device__ float  g_W2t[2 * 256 * 256];
__device__ float  g_mlp1[2 * BATCH * 256];
__device__ float  g_mlp2[2 * BATCH * 256];
__device__ int    g_sink;

// ---------------- PTX helpers ----------------
__device__ __forceinline__ unsigned smem_u32(const void* p) {
    unsigned a;
    asm("{ .reg .u64 t; cvta.to.shared.u64 t, %1; cvt.u32.u64 %0, t; }" : "=r"(a) : "l"(p));
    return a;
}
__device__ __forceinline__ void ldsm_x4(unsigned r[4], unsigned addr) {
    asm volatile("ldmatrix.sync.aligned.m8n8.x4.shared.b16 {%0,%1,%2,%3}, [%4];"
        : "=r"(r[0]), "=r"(r[1]), "=r"(r[2]), "=r"(r[3]) : "r"(addr));
}
__device__ __forceinline__ void ldsm_x4_t(unsigned r[4], unsigned addr) {
    asm volatile("ldmatrix.sync.aligned.m8n8.x4.trans.shared.b16 {%0,%1,%2,%3}, [%4];"
        : "=r"(r[0]), "=r"(r[1]), "=r"(r[2]), "=r"(r[3]) : "r"(addr));
}
__device__ __forceinline__ void mma16816(float c[4], const unsigned a[4],
                                         unsigned b0, unsigned b1) {
    asm volatile("mma.sync.aligned.m16n8k16.row.col.f32.f16.f16.f32 "
        "{%0,%1,%2,%3}, {%4,%5,%6,%7}, {%8,%9}, {%0,%1,%2,%3};"
        : "+f"(c[0]), "+f"(c[1]), "+f"(c[2]), "+f"(c[3])
        : "r"(a[0]), "r"(a[1]), "r"(a[2]), "r"(a[3]), "r"(b0), "r"(b1));
}

// ---------------- weight packing ----------------
// Rank slice: 96 cols = 2 col-groups x [r(16)|z(16)|p(16)] for 16 units each.
__global__ void prep_weights(const float* __restrict__ Wi, const float* __restrict__ Wh) {
    int idx = blockIdx.x * blockDim.x + threadIdx.x;
    const int NH = CSIZE * 256 * 96;
    const int NX = CSIZE * 80 * 96;
    if (idx < NH) {
        int rnk = idx / (256 * 96);
        int rem = idx % (256 * 96);
        int k = rem / 96, c = rem % 96;
        int wcg = c / 48, r2 = c % 48, panel = r2 / 16, uu = r2 % 16;
        int j = rnk * 32 + wcg * 16 + uu;
        g_Whp[idx] = __float2half(Wh[k * 768 + panel * 256 + j]);
    } else if (idx < NH + NX) {
        int i2 = idx - NH;
        int rnk = i2 / (80 * 96);
        int rem = i2 % (80 * 96);
        int k = rem / 96, c = rem % 96;
        int wcg = c / 48, r2 = c % 48, panel = r2 / 16, uu = r2 % 16;
        int j = rnk * 32 + wcg * 16 + uu;
        float w = (k < 65) ? Wi[k * 768 + panel * 256 + j] : 0.0f;
        g_Wxp[i2] = __float2half(w);
    }
}

__global__ void prep_mlp(const float* __restrict__ W1, const float* __restrict__ W2) {
    int idx = blockIdx.x * blockDim.x + threadIdx.x;
    const int N1 = 2 * 288 * 256;
    const int N2 = 2 * 256 * 256;
    if (idx < N1) {
        int c = idx / (288 * 256);
        int rem = idx % (288 * 256);
        int k = rem / 256, n = rem % 256;
        float w = (k < 265) ? W1[((size_t)c * 265 + k) * 256 + n] : 0.0f;
        g_W1t[idx] = wmma::__float_to_tf32(w);
    } else if (idx < N1 + N2) {
        g_W2t[idx - N1] = wmma::__float_to_tf32(W2[idx - N1]);
    }
}

__global__ void zero_h() {
    int i = blockIdx.x * blockDim.x + threadIdx.x;
    if (i < BATCH * HDIM) g_hpp[0][i] = __float2half(0.0f);
}

__global__ void warm_k(int v) {
    if (threadIdx.x == 0 && v == 123456789) g_sink = 1;  // never taken
}

// ---------------- persistent GRU: raw mma, sync-lean loop ----------------
__global__ void __cluster_dims__(CSIZE, 1, 1) __launch_bounds__(NTHREADS, 1)
gru_reg(const float* __restrict__ particles,   // [B,T,DP]
        const float* __restrict__ pweights,    // [B,T]
        const float* __restrict__ bi,          // [768]
        const float* __restrict__ bhn)         // [256]
{
    extern __shared__ char smem[];
    const unsigned sb = smem_u32(smem);
    char* HsB = smem + SM_HS;
    char* PsB = smem + SM_PS;

    const int tid  = threadIdx.x;
    const int lane = tid & 31;
    const int warp = tid >> 5;
    const int wr   = warp & 3;      // row pair: rows wr*16 .. wr*16+15
    const int wc   = warp >> 2;     // col group: cols wc*48
    const int rnk  = blockIdx.x & (CSIZE - 1);
    const int cl   = blockIdx.x >> 3;
    const int row0 = cl * MROWS;

    // ---- load weight slices into SMEM (once) ----
    for (int i = tid; i < 256 * 12; i += NTHREADS) {
        int r = i / 12, q = i % 12;
        *(uint4*)(smem + SM_WH + r * WS_STRIDE + q * 16) =
            *(const uint4*)(g_Whp + ((size_t)rnk * 256 + r) * 96 + q * 8);
    }
    for (int i = tid; i < 80 * 12; i += NTHREADS) {
        int r = i / 12, q = i % 12;
        *(uint4*)(smem + SM_WX + r * WS_STRIDE + q * 16) =
            *(const uint4*)(g_Wxp + ((size_t)rnk * 80 + r) * 96 + q * 8);
    }
    // ---- zero Ps pad cols 64..87 ----
    for (int i = tid; i < MROWS * 3; i += NTHREADS) {
        int r = i / 3, q = i % 3;
        *(uint4*)(PsB + r * PS_STRIDE + 128 + q * 16) = make_uint4(0, 0, 0, 0);
    }
    // ---- fill Ps for t=0 (block-wide; pre-loop sync covers it) ----
    for (int i = tid; i < MROWS * 16; i += NTHREADS) {
        int r = i >> 4, q = i & 15;
        float4 v = *(const float4*)(particles + ((size_t)(row0 + r) * TSTEPS + 0) * DPART + q * 4);
        __half2 h01 = __floats2half2_rn(v.x, v.y);
        __half2 h23 = __floats2half2_rn(v.z, v.w);
        *(uint2*)(PsB + r * PS_STRIDE + q * 8) =
            make_uint2(*(unsigned*)&h01, *(unsigned*)&h23);
    }
    if (tid < MROWS)
        *(__half*)(PsB + tid * PS_STRIDE + 128) =
            __float2half(pweights[(size_t)(row0 + tid) * TSTEPS + 0]);
    __syncthreads();

    // ---- per-thread ldmatrix base addresses ----
    const unsigned Ah = sb + SM_HS + (wr * 16 + (lane & 15)) * HS_STRIDE + (lane >> 4) * 16;
    const unsigned Ax = sb + SM_PS + (wr * 16 + (lane & 15)) * PS_STRIDE + (lane >> 4) * 16;
    const unsigned Bh = sb + SM_WH + (lane & 15) * WS_STRIDE + (wc * 48 + (lane >> 4) * 8) * 2;
    const unsigned Bx = sb + SM_WX + (lane & 15) * WS_STRIDE + (wc * 48 + (lane >> 4) * 8) * 2;

    // ---- ingest mapping: this warp owns 8 rows (wc half of the pair) ----
    const int irow = wr * 16 + wc * 8 + (lane >> 2);   // smem-local row
    const int grow_i = row0 + irow;                    // global row
    const int iq0 = lane & 3;                          // uint4 col phase

    // ---- per-thread epilogue constants ----
    const int ub    = (lane & 3) * 2;
    const int jbase = rnk * 32 + wc * 16;
    float bir[2][2], biz[2][2], bin[2][2], bhv[2][2];
#pragma unroll
    for (int nh = 0; nh < 2; ++nh)
#pragma unroll
        for (int pa = 0; pa < 2; ++pa) {
            int j = jbase + ub + nh * 8 + pa;
            bir[nh][pa] = bi[j];
            biz[nh][pa] = bi[256 + j];
            bin[nh][pa] = bi[512 + j];
            bhv[nh][pa] = bhn[j];
        }

    asm volatile("barrier.cluster.arrive.aligned;" ::: "memory");

    for (int t = 0; t < TSTEPS; ++t) {
        const int p = t & 1;

        float accP[3][2][4];   // panels r,z,hpn x n8-halves x 4 elems
        float accX[2][4];      // xn panel
#pragma unroll
        for (int pn = 0; pn < 3; ++pn)
#pragma unroll
            for (int nh = 0; nh < 2; ++nh)
#pragma unroll
                for (int e = 0; e < 4; ++e) accP[pn][nh][e] = 0.0f;
#pragma unroll
        for (int nh = 0; nh < 2; ++nh)
#pragma unroll
            for (int e = 0; e < 4; ++e) accX[nh][e] = 0.0f;

        // ---- x-GEMM (h-independent; hides barrier skew) ----
#pragma unroll
        for (int kk = 0; kk < 5; ++kk) {
            unsigned a[4];
            ldsm_x4(a, Ax + kk * 32);
#pragma unroll
            for (int pn = 0; pn < 3; ++pn) {
                unsigned b[4];
                ldsm_x4_t(b, Bx + kk * 16 * WS_STRIDE + pn * 32);
                float* c0 = (pn < 2) ? accP[pn][0] : accX[0];
                float* c1 = (pn < 2) ? accP[pn][1] : accX[1];
                mma16816(c0, a, b[0], b[1]);
                mma16816(c1, a, b[2], b[3]);
            }
        }

        // ---- wait: h_t visible in g_hpp[p]; also = partner past last epilogue ----
        asm volatile("barrier.cluster.wait.aligned;" ::: "memory");

        // ---- ingest own 8 rows of h_t (8 x LDG.cg + STS per lane) ----
        {
            const __half* __restrict__ hin = g_hpp[p];
#pragma unroll
            for (int k = 0; k < 8; ++k) {
                int q = iq0 + k * 4;
                uint4 v = __ldcg((const uint4*)(hin + (size_t)grow_i * HDIM + q * 8));
                *(uint4*)(HsB + irow * HS_STRIDE + q * 16) = v;
            }
        }
        // pair barrier: partner's 8 rows visible before ldmatrix
        asm volatile("bar.sync %0, 64;" :: "r"(1 + wr) : "memory");

        // ---- h-GEMM: accP += h_t[16,256] @ Wh_slice ----
#pragma unroll
        for (int kk = 0; kk < 16; ++kk) {
            unsigned a[4];
            ldsm_x4(a, Ah + kk * 32);
#pragma unroll
            for (int pn = 0; pn < 3; ++pn) {
                unsigned b[4];
                ldsm_x4_t(b, Bh + kk * 16 * WS_STRIDE + pn * 32);
                mma16816(accP[pn][0], a, b[0], b[1]);
                mma16816(accP[pn][1], a, b[2], b[3]);
            }
        }

        // ---- register gate epilogue + STG h_{t+1} ----
        __half* __restrict__ hout = g_hpp[p ^ 1];
#pragma unroll
        for (int nh = 0; nh < 2; ++nh) {
            const int jc = jbase + ub + nh * 8;
#pragma unroll
            for (int rr = 0; rr < 2; ++rr) {
                const int rloc = wr * 16 + (lane >> 2) + rr * 8;
                __half2 ho2 = *(const __half2*)(HsB + rloc * HS_STRIDE + jc * 2);
                float hov[2] = {__low2float(ho2), __high2float(ho2)};
                float hn[2];
#pragma unroll
                for (int s = 0; s < 2; ++s) {
                    int e = rr * 2 + s;
                    float rg = __fdividef(1.0f, 1.0f + __expf(-(accP[0][nh][e] + bir[nh][s])));
                    float zg = __fdividef(1.0f, 1.0f + __expf(-(accP[1][nh][e] + biz[nh][s])));
                    float a2 = (accX[nh][e] + bin[nh][s]) + rg * (accP[2][nh][e] + bhv[nh][s]);
                    a2 = fminf(fmaxf(a2, -15.0f), 15.0f);
                    float e2 = __expf(-2.0f * a2);
                    float ng = __fdividef(1.0f - e2, 1.0f + e2);
                    hn[s] = (1.0f - zg) * ng + zg * hov[s];
                }
                *(__half2*)(hout + (size_t)(row0 + rloc) * HDIM + jc) =
                    __floats2half2_rn(hn[0], hn[1]);
            }
        }

        // release h_{t+1} (and own epilogue reads of HsB)
        asm volatile("barrier.cluster.arrive.aligned;" ::: "memory");

        // ---- refill Ps(t+1): warp writes ALL 16 pair rows (wc-duplicated, identical bytes) ----
        if (t < TSTEPS - 1) {
#pragma unroll
            for (int k = 0; k < 8; ++k) {
                int idx = lane + k * 32;            // 0..255
                int r = wr * 16 + (idx >> 4);       // 16 pair rows
                int q = idx & 15;                   // 16 float4 chunks (64 cols)
                float4 v = *(const float4*)(particles +
                            ((size_t)(row0 + r) * TSTEPS + (t + 1)) * DPART + q * 4);
                __half2 h01 = __floats2half2_rn(v.x, v.y);
                __half2 h23 = __floats2half2_rn(v.z, v.w);
                *(uint2*)(PsB + r * PS_STRIDE + q * 8) =
                    make_uint2(*(unsigned*)&h01, *(unsigned*)&h23);
            }
            if (lane < 16) {
                int r = wr * 16 + lane;
                *(__half*)(PsB + r * PS_STRIDE + 128) =
                    __float2half(pweights[(size_t)(row0 + r) * TSTEPS + (t + 1)]);
            }
        }
    }
    // final h is in g_hpp[0] (256 steps, even)
}

// ---------------- MLP layers: tf32 wmma ----------------
__global__ void __launch_bounds__(256) mlp_layer_t(
    const float* __restrict__ action, const float* __restrict__ time_idx,
    const float* __restrict__ bias, int KP, int mode)
{
    __shared__ float As[64][40];
    __shared__ float Bs[32][72];
    __shared__ float stage[64][68];

    const int c = blockIdx.z;
    const int rowb = blockIdx.x * 64;
    const int colb = blockIdx.y * 64;
    const int tid = threadIdx.x;
    const int warp = tid >> 5;
    const int wr = warp & 3;
    const int wc = warp >> 2;

    wmma::fragment<wmma::accumulator, 16, 16, 8, float> acc[2];
    wmma::fill_fragment(acc[0], 0.0f);
    wmma::fill_fragment(acc[1], 0.0f);

    const float* Wsrc = (mode == 0) ? g_W1t + (size_t)c * 288 * 256
                                    : g_W2t + (size_t)c * 256 * 256;

    for (int k0 = 0; k0 < KP; k0 += 32) {
        for (int i = tid; i < 64 * 32; i += 256) {
            int r = i >> 5, k = i & 31;
            int d = k0 + k;
            float v = 0.0f;
            if (mode == 0) {
                if (d < 256)       v = __half2float(g_hpp[0][(size_t)(rowb + r) * HDIM + d]);
                else if (d < 264)  v = action[(rowb + r) * ADIM + (d - 256)];
                else if (d == 264) v = time_idx[rowb + r] * 0.01f;
            } else {
                v = g_mlp1[((size_t)c * BATCH + rowb + r) * 256 + d];
            }
            As[r][k] = wmma::__float_to_tf32(v);
        }
        for (int i = tid; i < 32 * 64; i += 256) {
            int kk = i >> 6, cc = i & 63;
            Bs[kk][cc] = Wsrc[(size_t)(k0 + kk) * 256 + colb + cc];
        }
        __syncthreads();
#pragma unroll
        for (int kk = 0; kk < 32; kk += 8) {
            wmma::fragment<wmma::matrix_a, 16, 16, 8, wmma::precision::tf32, wmma::row_major> af;
            wmma::load_matrix_sync(af, &As[wr * 16][kk], 40);
#pragma unroll
            for (int ct = 0; ct < 2; ct++) {
                wmma::fragment<wmma::matrix_b, 16, 16, 8, wmma::precision::tf32, wmma::row_major> bf;
                wmma::load_matrix_sync(bf, &Bs[kk][wc * 32 + ct * 16], 72);
                wmma::mma_sync(acc[ct], af, bf, acc[ct]);
            }
        }
        __syncthreads();
    }

#pragma unroll
    for (int ct = 0; ct < 2; ct++)
        wmma::store_matrix_sync(&stage[wr * 16][wc * 32 + ct * 16], acc[ct], 68,
                                wmma::mem_row_major);
    __syncthreads();

    float* dst = (mode == 0) ? g_mlp1 : g_mlp2;
    for (int i = tid; i < 64 * 64; i += 256) {
        int r = i >> 6, col = i & 63;
        float v = stage[r][col] + bias[c * 256 + colb + col];
        dst[((size_t)c * BATCH + rowb + r) * 256 + colb + col] = fmaxf(v, 0.0f);
    }
}

// ---------------- final projection ----------------
__global__ void mlp_out(const float* __restrict__ W3, const float* __restrict__ b3,
                        float* __restrict__ out)
{
    int gw   = (blockIdx.x * blockDim.x + threadIdx.x) >> 5;
    int lane = threadIdx.x & 31;
    if (gw >= 2 * BATCH) return;
    int c = gw >> 10;
    int b = gw & 1023;
    const float* v = g_mlp2 + ((size_t)c * BATCH + b) * 256;
    const float* w = W3 + (size_t)c * 256;
    float s = 0.0f;
    for (int i = lane; i < 256; i += 32) s += v[i] * w[i];
#pragma unroll
    for (int o = 16; o; o >>= 1) s += __shfl_xor_sync(0xffffffffu, s, o);
    if (lane == 0) out[b * 2 + c] = s + b3[c];
}

// ---------------- launch ----------------
extern "C" void kernel_launch(void* const* d_in, const int* in_sizes, int n_in,
                              void* d_out, int out_size)
{
    const float* particles = (const float*)d_in[0];
    const float* weights   = (const float*)d_in[1];
    const float* action    = (const float*)d_in[2];
    const float* time_idx  = (const float*)d_in[3];
    const float* Wi        = (const float*)d_in[4];
    const float* bi        = (const float*)d_in[5];
    const float* Wh        = (const float*)d_in[6];
    const float* bhn       = (const float*)d_in[7];
    const float* W1        = (const float*)d_in[8];
    const float* b1        = (const float*)d_in[9];
    const float* W2        = (const float*)d_in[10];
    const float* b2        = (const float*)d_in[11];
    const float* W3        = (const float*)d_in[12];
    const float* b3        = (const float*)d_in[13];
    float* out = (float*)d_out;

    cudaFuncSetAttribute(gru_reg, cudaFuncAttributeMaxDynamicSharedMemorySize, SMEM_BYTES);

    const int NWT = CSIZE * 256 * 96 + CSIZE * 80 * 96;
    prep_weights<<<(NWT + 255) / 256, 256>>>(Wi, Wh);                        // idx 0
    prep_mlp<<<(2 * 288 * 256 + 2 * 256 * 256 + 255) / 256, 256>>>(W1, W2);  // idx 1
    zero_h<<<(BATCH * HDIM + 255) / 256, 256>>>();                           // idx 2
    warm_k<<<1, 32>>>(0);                                                    // idx 3
    gru_reg<<<NCLUST * CSIZE, NTHREADS, SMEM_BYTES>>>(particles, weights, bi, bhn); // idx 4 (ncu)

    mlp_layer_t<<<dim3(16, 4, 2), 256>>>(action, time_idx, b1, 288, 0);
    mlp_layer_t<<<dim3(16, 4, 2), 256>>>(action, time_idx, b2, 256, 1);
    mlp_out<<<(2 * BATCH * 32 + 255) / 256, 256>>>(W3, b3, out);
}